// round 11
// baseline (speedup 1.0000x reference)
#include <cuda_runtime.h>

// ObservabilityWeightedMSE — weighted-MSE reduction, two launches.
// d_in[0]=predictions [500000,82] f32, d_in[1]=targets [500000,82] f32,
// d_in[2]=inputs [500000,400] f32. Output: scalar f32.
//
// Locked-in: two-launch family (fused tails cost 15-23us); atomicAdd(double)
// per block + <<<1,1>>> finalize (R10, 163.2us record); launch_bounds(256,8).
// R11: inputs loaded as 3 fully-coalesced LDG.128 fronts over bytes [0,1536)
//      of each row (same DRAM lines as the old 80B-span gather, but full-line
//      4-sector bursts). Node-below test rebuilt from 3 ballots + 96-bit scan.

#define THRESH   1e-4f
#define NCOLS    82
#define ROW_IN   400
#define NBLOCKS  1184
#define NTHREADS 256

// float4-index validity masks: bit l set iff (32k+l) % 10 < 5  (magnitude half)
#define VALID0 0xC1F07C1Fu
#define VALID1 0xF07C1F07u
#define VALID2 0x7C1F07C1u

__device__ double g_acc = 0.0;   // reset by finalize after each use

__global__ void __launch_bounds__(NTHREADS, 8)   // cap regs at 32: 8 blocks/SM
wmse_kernel(const float* __restrict__ pred,
            const float* __restrict__ targ,
            const float* __restrict__ inp,
            int B)
{
    const int lane  = threadIdx.x & 31;
    const int warp  = threadIdx.x >> 5;
    const int gwarp = blockIdx.x * (NTHREADS / 32) + warp;
    const int nwarp = NBLOCKS * (NTHREADS / 32);

    float acc = 0.0f;

    for (int r = gwarp; r < B; r += nwarp) {
        // ---- inputs: coalesced full-front load of float4 idx [0,96) ----
        // needed magnitude bytes [160n,160n+80) all lie in [0,1536).
        const float4* pin4 = (const float4*)(inp + (size_t)r * ROW_IN);

        float4 v0 = pin4[lane];
        float4 v1 = pin4[32 + lane];
        float4 v2 = pin4[64 + lane];

        bool m0 = fmaxf(fmaxf(v0.x, v0.y), fmaxf(v0.z, v0.w)) >= THRESH;
        bool m1 = fmaxf(fmaxf(v1.x, v1.y), fmaxf(v1.z, v1.w)) >= THRESH;
        bool m2 = fmaxf(fmaxf(v2.x, v2.y), fmaxf(v2.z, v2.w)) >= THRESH;

        unsigned b0 = __ballot_sync(0xffffffffu, m0) & VALID0;
        unsigned b1 = __ballot_sync(0xffffffffu, m1) & VALID1;
        unsigned b2 = __ballot_sync(0xffffffffu, m2) & VALID2;

        // 96-bit ok-field: node n ok <=> any bit in [10n, 10n+10)
        unsigned long long lo = (unsigned long long)b0 |
                                ((unsigned long long)b1 << 32);
        unsigned long long hi = (lo >> 60) | ((unsigned long long)b2 << 4);
        unsigned ok = 0;
        #pragma unroll
        for (int n = 0; n < 6; ++n)
            if ((unsigned)(lo >> (10 * n)) & 0x3FFu) ok |= 1u << n;
        #pragma unroll
        for (int n = 0; n < 4; ++n)
            if ((unsigned)(hi >> (10 * n)) & 0x3FFu) ok |= 1u << (6 + n);

        unsigned below = (~ok) & 0x3FFu;
        // below==0 -> ffs(0x400)=11 -> cut=44 > max col 40 -> never cuts
        const int cut = __ffs(below | 0x400u) << 2;

        // ---- weighted MSE over 82 columns, coalesced scalar loads ----
        const float* pp = pred + (size_t)r * NCOLS;
        const float* pt = targ + (size_t)r * NCOLS;
        #pragma unroll
        for (int it = 0; it < 3; ++it) {
            int c = it * 32 + lane;
            if (c < NCOLS) {
                float d = pp[c] - pt[c];
                bool five; int col;
                if (c < 41) { col = c; five = ((c & 3) == 0); }
                else {
                    int j = c - 41; col = j;
                    five = ((j & 3) == 3) || (((j & 3) == 0) && (j != 40));
                }
                float w = five ? 5.0f : 1.0f;
                if (col >= cut) w *= 0.1f;
                acc = fmaf(d * d, w, acc);
            }
        }
    }

    // ---- block reduction -> one double atomic per block ----
    #pragma unroll
    for (int o = 16; o > 0; o >>= 1)
        acc += __shfl_down_sync(0xffffffffu, acc, o);

    __shared__ float smem[NTHREADS / 32];
    if (lane == 0) smem[warp] = acc;
    __syncthreads();
    if (warp == 0) {
        float v = (lane < (NTHREADS / 32)) ? smem[lane] : 0.0f;
        #pragma unroll
        for (int o = 4; o > 0; o >>= 1)
            v += __shfl_down_sync(0xffffffffu, v, o);
        if (lane == 0) atomicAdd(&g_acc, (double)v);
    }
}

// Minimal finalize: read accumulator, scale, write output, reset for next replay.
__global__ void finalize_kernel(float* __restrict__ out, double inv_total)
{
    out[0] = (float)(g_acc * inv_total);
    g_acc  = 0.0;
}

extern "C" void kernel_launch(void* const* d_in, const int* in_sizes, int n_in,
                              void* d_out, int out_size)
{
    const float* pred = (const float*)d_in[0];
    const float* targ = (const float*)d_in[1];
    const float* inp  = (const float*)d_in[2];
    float* out = (float*)d_out;

    const int B = in_sizes[0] / NCOLS;   // 500000

    wmse_kernel<<<NBLOCKS, NTHREADS>>>(pred, targ, inp, B);
    finalize_kernel<<<1, 1>>>(out, 1.0 / ((double)B * NCOLS));
}